// round 1
// baseline (speedup 1.0000x reference)
#include <cuda_runtime.h>
#include <cuda_bf16.h>

// ---------------------------------------------------------------------------
// EnhancedReconstructionLoss: 0.8*MSE + 0.2*(1 - mean(SSIM_map))
// 3x3 avg pool, stride 1, zero pad, divisor always 9 (count_include_pad).
//
// Strategy: vertical-first separable window sums with a 3-row rolling register
// window (no smem), horizontal 3-sums via warp shuffles + per-warp halo column,
// all heavy math in packed f32x2 (Blackwell FFMA2 path).
// ---------------------------------------------------------------------------

#define Wd 512
#define Hd 512
#define NCp 96
#define ROWS 32
#define STRIPS (Hd / ROWS)          // 16
#define NBLK (NCp * STRIPS)         // 1536
#define NTOT 25165824.0             // 32*3*512*512

__device__ float g_pmse[NBLK];
__device__ float g_pssim[NBLK];

typedef unsigned long long u64;

__device__ __forceinline__ u64 f2_pack(float lo, float hi) {
    u64 r;
    asm("mov.b64 %0, {%1, %2};" : "=l"(r) : "f"(lo), "f"(hi));
    return r;
}
__device__ __forceinline__ void f2_unpack(u64 p, float& lo, float& hi) {
    asm("mov.b64 {%0, %1}, %2;" : "=f"(lo), "=f"(hi) : "l"(p));
}
__device__ __forceinline__ u64 f2_set(float v) { return f2_pack(v, v); }
__device__ __forceinline__ u64 add2(u64 a, u64 b) {
    u64 d; asm("add.rn.f32x2 %0, %1, %2;" : "=l"(d) : "l"(a), "l"(b)); return d;
}
__device__ __forceinline__ u64 mul2(u64 a, u64 b) {
    u64 d; asm("mul.rn.f32x2 %0, %1, %2;" : "=l"(d) : "l"(a), "l"(b)); return d;
}
__device__ __forceinline__ u64 fma2(u64 a, u64 b, u64 c) {
    u64 d; asm("fma.rn.f32x2 %0, %1, %2, %3;" : "=l"(d) : "l"(a), "l"(b), "l"(c)); return d;
}
__device__ __forceinline__ u64 neg2(u64 a) { return a ^ 0x8000000080000000ULL; }

// Horizontal 3-sum of a packed vertical-sum quartet (va=(v0,v1), vb=(v2,v3)),
// using warp shuffles for cross-lane neighbors and vH for warp-edge halo.
__device__ __forceinline__ void hsum3(u64 va, u64 vb, float vH, int lane,
                                      u64& Ha, u64& Hb) {
    float v0, v1, v2, v3;
    f2_unpack(va, v0, v1);
    f2_unpack(vb, v2, v3);
    float nl = __shfl_up_sync(0xffffffffu, v3, 1);
    float nr = __shfl_down_sync(0xffffffffu, v0, 1);
    nl = (lane == 0)  ? vH : nl;
    nr = (lane == 31) ? vH : nr;
    u64 S0 = f2_pack(nl, v0);
    u64 S1 = f2_pack(v1, v2);
    u64 S2 = f2_pack(v3, nr);
    Ha = add2(add2(S0, va), S1);   // (nl+v0+v1, v0+v1+v2)
    Hb = add2(add2(S1, vb), S2);   // (v1+v2+v3, v2+v3+nr)
}

__global__ void __launch_bounds__(128)
loss_main(const float* __restrict__ X, const float* __restrict__ Y) {
    const int plane = blockIdx.y;
    const int strip = blockIdx.x;
    const int R0 = strip * ROWS;
    const int w = threadIdx.x >> 5;
    const int lane = threadIdx.x & 31;
    const int c0 = (w << 7) + (lane << 2);

    const float* px = X + (size_t)plane * (Wd * Hd);
    const float* py = Y + (size_t)plane * (Wd * Hd);

    const bool hv = (lane == 0) ? (c0 > 0)
                  : ((lane == 31) ? (c0 + 4 < Wd) : false);
    const int hcol = (lane == 0) ? (c0 - 1) : (c0 + 4);

    // Folded constants: 81*C1, 81*C2, 81^2*EPS
    const u64 k2   = f2_set(2.0f);
    const u64 km2  = f2_set(-2.0f);
    const u64 k18  = f2_set(18.0f);
    const u64 k9   = f2_set(9.0f);
    const u64 kc1  = f2_set(0.0081f);
    const u64 kc2  = f2_set(0.0729f);
    const u64 keps = f2_set(6.561e-5f);

    auto ld4v = [&](const float* p, int r, bool extra) -> float4 {
        float4 z = make_float4(0.f, 0.f, 0.f, 0.f);
        if (extra && (unsigned)r < (unsigned)Hd)
            z = *reinterpret_cast<const float4*>(p + (size_t)r * Wd + c0);
        return z;
    };
    auto ldh = [&](const float* p, int r, bool extra) -> float {
        return (hv && extra && (unsigned)r < (unsigned)Hd)
                   ? p[(size_t)r * Wd + hcol] : 0.f;
    };

    // Prime the rolling window: rows R0-1, R0, R0+1; prefetch R0+2.
    float4 f;
    f = ld4v(px, R0 - 1, true); u64 xm1a = f2_pack(f.x, f.y), xm1b = f2_pack(f.z, f.w);
    f = ld4v(px, R0    , true); u64 x0a  = f2_pack(f.x, f.y), x0b  = f2_pack(f.z, f.w);
    f = ld4v(px, R0 + 1, true); u64 xp1a = f2_pack(f.x, f.y), xp1b = f2_pack(f.z, f.w);
    f = ld4v(py, R0 - 1, true); u64 ym1a = f2_pack(f.x, f.y), ym1b = f2_pack(f.z, f.w);
    f = ld4v(py, R0    , true); u64 y0a  = f2_pack(f.x, f.y), y0b  = f2_pack(f.z, f.w);
    f = ld4v(py, R0 + 1, true); u64 yp1a = f2_pack(f.x, f.y), yp1b = f2_pack(f.z, f.w);
    float4 nfx = ld4v(px, R0 + 2, true);
    float4 nfy = ld4v(py, R0 + 2, true);

    float hxm1 = ldh(px, R0 - 1, true), hx0 = ldh(px, R0, true), hxp1 = ldh(px, R0 + 1, true);
    float hym1 = ldh(py, R0 - 1, true), hy0 = ldh(py, R0, true), hyp1 = ldh(py, R0 + 1, true);
    float nhx = ldh(px, R0 + 2, true);
    float nhy = ldh(py, R0 + 2, true);

    u64 accma = f2_pack(0.f, 0.f), accmb = f2_pack(0.f, 0.f);
    float as0 = 0.f, as1 = 0.f;

    for (int r = R0; r < R0 + ROWS; ++r) {
        // ---- vertical 3-sums (packed) ----
        u64 vxa  = add2(add2(xm1a, x0a), xp1a);
        u64 vxb  = add2(add2(xm1b, x0b), xp1b);
        u64 vya  = add2(add2(ym1a, y0a), yp1a);
        u64 vyb  = add2(add2(ym1b, y0b), yp1b);
        u64 vxxa = fma2(xm1a, xm1a, fma2(x0a, x0a, mul2(xp1a, xp1a)));
        u64 vxxb = fma2(xm1b, xm1b, fma2(x0b, x0b, mul2(xp1b, xp1b)));
        u64 vyya = fma2(ym1a, ym1a, fma2(y0a, y0a, mul2(yp1a, yp1a)));
        u64 vyyb = fma2(ym1b, ym1b, fma2(y0b, y0b, mul2(yp1b, yp1b)));
        u64 vxya = fma2(xm1a, ym1a, fma2(x0a, y0a, mul2(xp1a, yp1a)));
        u64 vxyb = fma2(xm1b, ym1b, fma2(x0b, y0b, mul2(xp1b, yp1b)));

        // ---- halo column vertical sums (scalar; meaningful on lanes 0/31) ----
        float vHx  = hxm1 + hx0 + hxp1;
        float vHy  = hym1 + hy0 + hyp1;
        float vHxx = fmaf(hxm1, hxm1, fmaf(hx0, hx0, hxp1 * hxp1));
        float vHyy = fmaf(hym1, hym1, fmaf(hy0, hy0, hyp1 * hyp1));
        float vHxy = fmaf(hxm1, hym1, fmaf(hx0, hy0, hxp1 * hyp1));

        // ---- horizontal 3-sums ----
        u64 Sxa, Sxb, Sya, Syb, Sxxa, Sxxb, Syya, Syyb, Sxya, Sxyb;
        hsum3(vxa,  vxb,  vHx,  lane, Sxa,  Sxb);
        hsum3(vya,  vyb,  vHy,  lane, Sya,  Syb);
        hsum3(vxxa, vxxb, vHxx, lane, Sxxa, Sxxb);
        hsum3(vyya, vyyb, vHyy, lane, Syya, Syyb);
        hsum3(vxya, vxyb, vHxy, lane, Sxya, Sxyb);

        // ---- SSIM for each packed pair ----
        // ssim = (2SxSy+81C1)(18Sxy-2SxSy+81C2) /
        //        ((Sx^2+Sy^2+81C1)(9(Sxx+Syy)-(Sx^2+Sy^2)+81C2) + 81^2 eps)
        {
            u64 P  = mul2(Sxa, Sya);
            u64 A  = fma2(P, k2, kc1);
            u64 T  = fma2(Sxya, k18, kc2);
            u64 Q  = fma2(P, km2, T);
            u64 U  = mul2(Sxa, Sxa);
            u64 B  = fma2(Sya, Sya, U);
            u64 Bc = add2(B, kc1);
            u64 Wt = add2(Sxxa, Syya);
            u64 R  = fma2(Wt, k9, kc2);
            u64 R2 = add2(R, neg2(B));
            u64 num = mul2(A, Q);
            u64 den = fma2(Bc, R2, keps);
            float n0, n1, d0, d1;
            f2_unpack(num, n0, n1);
            f2_unpack(den, d0, d1);
            as0 += __fdividef(n0, d0);
            as1 += __fdividef(n1, d1);
        }
        {
            u64 P  = mul2(Sxb, Syb);
            u64 A  = fma2(P, k2, kc1);
            u64 T  = fma2(Sxyb, k18, kc2);
            u64 Q  = fma2(P, km2, T);
            u64 U  = mul2(Sxb, Sxb);
            u64 B  = fma2(Syb, Syb, U);
            u64 Bc = add2(B, kc1);
            u64 Wt = add2(Sxxb, Syyb);
            u64 R  = fma2(Wt, k9, kc2);
            u64 R2 = add2(R, neg2(B));
            u64 num = mul2(A, Q);
            u64 den = fma2(Bc, R2, keps);
            float n0, n1, d0, d1;
            f2_unpack(num, n0, n1);
            f2_unpack(den, d0, d1);
            as0 += __fdividef(n0, d0);
            as1 += __fdividef(n1, d1);
        }

        // ---- MSE on the center row ----
        u64 da = add2(x0a, neg2(y0a));
        u64 db = add2(x0b, neg2(y0b));
        accma = fma2(da, da, accma);
        accmb = fma2(db, db, accmb);

        // ---- rotate window, consume prefetch, issue next prefetch ----
        xm1a = x0a; xm1b = x0b; x0a = xp1a; x0b = xp1b;
        xp1a = f2_pack(nfx.x, nfx.y); xp1b = f2_pack(nfx.z, nfx.w);
        ym1a = y0a; ym1b = y0b; y0a = yp1a; y0b = yp1b;
        yp1a = f2_pack(nfy.x, nfy.y); yp1b = f2_pack(nfy.z, nfy.w);
        hxm1 = hx0; hx0 = hxp1; hxp1 = nhx;
        hym1 = hy0; hy0 = hyp1; hyp1 = nhy;

        int rl = r + 3;
        bool pv = (rl <= R0 + ROWS);   // don't over-read past the strip
        nfx = ld4v(px, rl, pv);
        nfy = ld4v(py, rl, pv);
        nhx = ldh(px, rl, pv);
        nhy = ldh(py, rl, pv);
    }

    // ---- block reduction ----
    float m0, m1, m2, m3;
    f2_unpack(accma, m0, m1);
    f2_unpack(accmb, m2, m3);
    float msum = (m0 + m1) + (m2 + m3);
    float ssum = as0 + as1;
#pragma unroll
    for (int o = 16; o; o >>= 1) {
        msum += __shfl_xor_sync(0xffffffffu, msum, o);
        ssum += __shfl_xor_sync(0xffffffffu, ssum, o);
    }
    __shared__ float red[8];
    if (lane == 0) { red[w] = msum; red[4 + w] = ssum; }
    __syncthreads();
    if (threadIdx.x == 0) {
        float M = (red[0] + red[1]) + (red[2] + red[3]);
        float S = (red[4] + red[5]) + (red[6] + red[7]);
        int bid = plane * STRIPS + strip;
        g_pmse[bid] = M;
        g_pssim[bid] = S;
    }
}

__global__ void finalize_kernel(float* __restrict__ out) {
    __shared__ double sm[512];
    __shared__ double ss[512];
    int t = threadIdx.x;
    double m = 0.0, s = 0.0;
    for (int i = t; i < NBLK; i += 512) {
        m += (double)g_pmse[i];
        s += (double)g_pssim[i];
    }
    sm[t] = m; ss[t] = s;
    __syncthreads();
    for (int o = 256; o; o >>= 1) {
        if (t < o) { sm[t] += sm[t + o]; ss[t] += ss[t + o]; }
        __syncthreads();
    }
    if (t == 0) {
        double inv = 1.0 / NTOT;
        double mse = sm[0] * inv;
        double ssim_mean = ss[0] * inv;
        out[0] = (float)(0.8 * mse + 0.2 * (1.0 - ssim_mean));
    }
}

extern "C" void kernel_launch(void* const* d_in, const int* in_sizes, int n_in,
                              void* d_out, int out_size) {
    const float* X = (const float*)d_in[0];
    const float* Y = (const float*)d_in[1];
    dim3 grid(STRIPS, NCp);
    dim3 block(128);
    loss_main<<<grid, block>>>(X, Y);
    finalize_kernel<<<1, 512>>>((float*)d_out);
}

// round 2
// speedup vs baseline: 1.1978x; 1.1978x over previous
#include <cuda_runtime.h>

// ---------------------------------------------------------------------------
// EnhancedReconstructionLoss: 0.8*MSE + 0.2*(1 - mean(SSIM_map)), fused.
//
// s/d reformulation: with s=x+y, d=x-y only 4 window sums needed (Ws,Wd,Wss,Wdd):
//   N1 = (Ws^2-Wd^2) + 162*C1          N2 = 9(Wss-Wdd) - (Ws^2-Wd^2) + 162*C2
//   D1 = (Ws^2+Wd^2) + 162*C1          D2 = 9(Wss+Wdd) - (Ws^2+Wd^2) + 162*C2
//   ssim = N1*N2 / (D1*D2 + 4*6561*eps)
// Each warp owns a 16-row x 256-col strip (8 cols/lane), rolling 4-slot
// vertical window fully unrolled, packed f32x2 math, single kernel with
// atomic finalize (arrival counter, self-resetting).
// ---------------------------------------------------------------------------

typedef unsigned long long u64;

#define IMW 512
#define IMH 512
#define NPLANES 96
#define RPW 16                    // rows per warp-task
#define STRIPS 32                 // 512 / 16
#define WPB 4                     // warps per block
#define NBLOCKS (NPLANES * STRIPS * 2 / WPB)   // 1536
#define NTOTD 25165824.0          // 32*3*512*512

__device__ float g_mse_acc  = 0.f;
__device__ float g_ssim_acc = 0.f;
__device__ unsigned int g_cnt = 0u;

__device__ __forceinline__ u64 f2_pack(float lo, float hi) {
    u64 r; asm("mov.b64 %0, {%1, %2};" : "=l"(r) : "f"(lo), "f"(hi)); return r;
}
__device__ __forceinline__ void f2_unpack(u64 p, float& lo, float& hi) {
    asm("mov.b64 {%0, %1}, %2;" : "=f"(lo), "=f"(hi) : "l"(p));
}
__device__ __forceinline__ u64 f2_set(float v) { return f2_pack(v, v); }
__device__ __forceinline__ u64 add2(u64 a, u64 b) {
    u64 d; asm("add.rn.f32x2 %0, %1, %2;" : "=l"(d) : "l"(a), "l"(b)); return d;
}
__device__ __forceinline__ u64 mul2(u64 a, u64 b) {
    u64 d; asm("mul.rn.f32x2 %0, %1, %2;" : "=l"(d) : "l"(a), "l"(b)); return d;
}
__device__ __forceinline__ u64 fma2(u64 a, u64 b, u64 c) {
    u64 d; asm("fma.rn.f32x2 %0, %1, %2, %3;" : "=l"(d) : "l"(a), "l"(b), "l"(c)); return d;
}

// Horizontal 3-sum over 8 columns held as 4 packed u64, with warp-shuffle
// neighbors and a scalar halo value vH at the warp's interior boundary.
// half==0: warp covers cols [0,256): left edge is image pad(0), right needs vH.
// half==1: warp covers cols [256,512): left needs vH, right edge is pad(0).
__device__ __forceinline__ void hsum8(const u64 v0, const u64 v1, const u64 v2, const u64 v3,
                                      float vH, int lane, int half,
                                      u64& H0, u64& H1, u64& H2, u64& H3) {
    float f0, f1, f2, f3, f4, f5, f6, f7;
    f2_unpack(v0, f0, f1);
    f2_unpack(v1, f2, f3);
    f2_unpack(v2, f4, f5);
    f2_unpack(v3, f6, f7);
    float up = __shfl_up_sync(0xffffffffu, f7, 1);
    float dn = __shfl_down_sync(0xffffffffu, f0, 1);
    float nl = (lane == 0)  ? (half ? vH : 0.f) : up;
    float nr = (lane == 31) ? (half ? 0.f : vH) : dn;
    u64 L0 = f2_pack(nl, f0);
    u64 L1 = f2_pack(f1, f2);
    u64 L2 = f2_pack(f3, f4);
    u64 L3 = f2_pack(f5, f6);
    u64 R3 = f2_pack(f7, nr);
    H0 = add2(add2(L0, v0), L1);   // R0 == L1
    H1 = add2(add2(L1, v1), L2);   // R1 == L2
    H2 = add2(add2(L2, v2), L3);   // R2 == L3
    H3 = add2(add2(L3, v3), R3);
}

__global__ void __launch_bounds__(128)
loss_fused(const float* __restrict__ X, const float* __restrict__ Y,
           float* __restrict__ out) {
    const int w    = threadIdx.x >> 5;
    const int lane = threadIdx.x & 31;
    const int task  = blockIdx.x * WPB + w;
    const int half  = task & 1;
    const int strip = (task >> 1) & (STRIPS - 1);
    const int plane = task >> 6;
    const int R0 = strip * RPW;
    const int c0 = half * 256 + (lane << 3);

    const float* px = X + (size_t)plane * (IMW * IMH) + c0;
    const float* py = Y + (size_t)plane * (IMW * IMH) + c0;

    const bool hval = (lane == 0) ? (half == 1)
                    : ((lane == 31) ? (half == 0) : false);
    const int hoff = (lane == 0) ? -1 : 8;

    const u64 km1  = f2_set(-1.0f);
    const u64 k9   = f2_set(9.0f);
    const u64 kC1  = f2_set(0.0162f);      // 162 * C1
    const u64 kC2  = f2_set(0.1458f);      // 162 * C2
    const u64 kEPS = f2_set(2.6244e-4f);   // 4 * 6561 * eps

    // 4-slot rolling window of s,d rows (8 cols = 4 u64 each) + halo scalars.
    u64 ws[4][4], wdv[4][4];
    float whs[4], whd[4];

    // Load input row gr = R0-1+j into slot j&3 (zeros outside the image).
    auto LOAD = [&](int j) {
        const int slot = j & 3;
        const int gr = R0 - 1 + j;
        const bool v = ((unsigned)gr < (unsigned)IMH);
        float4 xa = make_float4(0.f, 0.f, 0.f, 0.f), xb = xa, ya = xa, yb = xa;
        if (v) {
            const float4* p4 = reinterpret_cast<const float4*>(px + (size_t)gr * IMW);
            const float4* q4 = reinterpret_cast<const float4*>(py + (size_t)gr * IMW);
            xa = p4[0]; xb = p4[1];
            ya = q4[0]; yb = q4[1];
        }
        float hx = 0.f, hy = 0.f;
        if (v && hval) {
            hx = px[(size_t)gr * IMW + hoff];
            hy = py[(size_t)gr * IMW + hoff];
        }
        u64 xp0 = f2_pack(xa.x, xa.y), xp1 = f2_pack(xa.z, xa.w);
        u64 xp2 = f2_pack(xb.x, xb.y), xp3 = f2_pack(xb.z, xb.w);
        u64 yp0 = f2_pack(ya.x, ya.y), yp1 = f2_pack(ya.z, ya.w);
        u64 yp2 = f2_pack(yb.x, yb.y), yp3 = f2_pack(yb.z, yb.w);
        ws[slot][0] = add2(xp0, yp0);   wdv[slot][0] = fma2(yp0, km1, xp0);
        ws[slot][1] = add2(xp1, yp1);   wdv[slot][1] = fma2(yp1, km1, xp1);
        ws[slot][2] = add2(xp2, yp2);   wdv[slot][2] = fma2(yp2, km1, xp2);
        ws[slot][3] = add2(xp3, yp3);   wdv[slot][3] = fma2(yp3, km1, xp3);
        whs[slot] = hx + hy;
        whd[slot] = hx - hy;
    };

    LOAD(0); LOAD(1); LOAD(2);

    u64 mAcc0 = f2_set(0.f), mAcc1 = f2_set(0.f);
    float sAcc = 0.f;

#pragma unroll
    for (int r = 0; r < RPW; ++r) {
        if (r + 3 <= RPW + 1) LOAD(r + 3);   // prefetch next input row

        const int j0 = r & 3, j1 = (r + 1) & 3, j2 = (r + 2) & 3;

        // ---- vertical 3-sums ----
        u64 Vs[4], Vd[4], Vss[4], Vdd[4];
#pragma unroll
        for (int k = 0; k < 4; ++k) {
            u64 s0 = ws[j0][k], s1 = ws[j1][k], s2 = ws[j2][k];
            u64 d0 = wdv[j0][k], d1 = wdv[j1][k], d2 = wdv[j2][k];
            Vs[k]  = add2(add2(s0, s1), s2);
            Vd[k]  = add2(add2(d0, d1), d2);
            Vss[k] = fma2(s0, s0, fma2(s1, s1, mul2(s2, s2)));
            Vdd[k] = fma2(d0, d0, fma2(d1, d1, mul2(d2, d2)));
        }
        // halo vertical sums (only lanes 0/31 consume)
        float hs0 = whs[j0], hs1 = whs[j1], hs2 = whs[j2];
        float hd0 = whd[j0], hd1 = whd[j1], hd2 = whd[j2];
        float vHs  = hs0 + hs1 + hs2;
        float vHd  = hd0 + hd1 + hd2;
        float vHss = fmaf(hs0, hs0, fmaf(hs1, hs1, hs2 * hs2));
        float vHdd = fmaf(hd0, hd0, fmaf(hd1, hd1, hd2 * hd2));

        // ---- horizontal 3-sums ----
        u64 Hs[4], Hdq[4], Hss[4], Hdd[4];
        hsum8(Vs[0],  Vs[1],  Vs[2],  Vs[3],  vHs,  lane, half, Hs[0],  Hs[1],  Hs[2],  Hs[3]);
        hsum8(Vd[0],  Vd[1],  Vd[2],  Vd[3],  vHd,  lane, half, Hdq[0], Hdq[1], Hdq[2], Hdq[3]);
        hsum8(Vss[0], Vss[1], Vss[2], Vss[3], vHss, lane, half, Hss[0], Hss[1], Hss[2], Hss[3]);
        hsum8(Vdd[0], Vdd[1], Vdd[2], Vdd[3], vHdd, lane, half, Hdd[0], Hdd[1], Hdd[2], Hdd[3]);

        // ---- SSIM rational per packed pair ----
#pragma unroll
        for (int k = 0; k < 4; ++k) {
            u64 E  = mul2(Hs[k], Hs[k]);
            u64 F  = mul2(Hdq[k], Hdq[k]);
            u64 T1 = fma2(F, km1, E);          // E - F
            u64 T2 = add2(E, F);
            u64 N1 = add2(T1, kC1);
            u64 D1 = add2(T2, kC1);
            u64 U1 = fma2(Hdd[k], km1, Hss[k]); // Wss - Wdd
            u64 U2 = add2(Hss[k], Hdd[k]);
            u64 N2 = fma2(T1, km1, fma2(U1, k9, kC2));
            u64 D2 = fma2(T2, km1, fma2(U2, k9, kC2));
            u64 num = mul2(N1, N2);
            u64 den = fma2(D1, D2, kEPS);
            float n0, n1, d0, d1;
            f2_unpack(num, n0, n1);
            f2_unpack(den, d0, d1);
            sAcc += __fdividef(n0, d0);
            sAcc += __fdividef(n1, d1);
        }

        // ---- MSE on the center row (input row R0+r = slot j1) ----
        mAcc0 = fma2(wdv[j1][0], wdv[j1][0], mAcc0);
        mAcc0 = fma2(wdv[j1][1], wdv[j1][1], mAcc0);
        mAcc1 = fma2(wdv[j1][2], wdv[j1][2], mAcc1);
        mAcc1 = fma2(wdv[j1][3], wdv[j1][3], mAcc1);
    }

    // ---- reductions ----
    float m0, m1, m2, m3;
    f2_unpack(mAcc0, m0, m1);
    f2_unpack(mAcc1, m2, m3);
    float mAcc = (m0 + m1) + (m2 + m3);
#pragma unroll
    for (int o = 16; o; o >>= 1) {
        mAcc += __shfl_xor_sync(0xffffffffu, mAcc, o);
        sAcc += __shfl_xor_sync(0xffffffffu, sAcc, o);
    }
    __shared__ float shm[WPB], shs[WPB];
    if (lane == 0) { shm[w] = mAcc; shs[w] = sAcc; }
    __syncthreads();
    if (threadIdx.x == 0) {
        float M = (shm[0] + shm[1]) + (shm[2] + shm[3]);
        float S = (shs[0] + shs[1]) + (shs[2] + shs[3]);
        atomicAdd(&g_mse_acc, M);
        atomicAdd(&g_ssim_acc, S);
        __threadfence();
        unsigned c = atomicInc(&g_cnt, NBLOCKS - 1);   // wraps to 0 on last
        if (c == NBLOCKS - 1) {
            __threadfence();
            float Mt = atomicExch(&g_mse_acc, 0.f);
            float St = atomicExch(&g_ssim_acc, 0.f);
            double mse  = (double)Mt / NTOTD;
            double ssim = (double)St / NTOTD;
            out[0] = (float)(0.8 * mse + 0.2 * (1.0 - ssim));
        }
    }
}

extern "C" void kernel_launch(void* const* d_in, const int* in_sizes, int n_in,
                              void* d_out, int out_size) {
    const float* X = (const float*)d_in[0];
    const float* Y = (const float*)d_in[1];
    loss_fused<<<NBLOCKS, 128>>>(X, Y, (float*)d_out);
}